// round 15
// baseline (speedup 1.0000x reference)
#include <cuda_runtime.h>
#include <cuda_bf16.h>
#include <cstdint>

#define N_MAX 100000
#define E_MAX 1600000
#define D 128

// ---------------- scratch (device globals; no allocation allowed) ----------
__device__ float g_bufA[N_MAX * D];
__device__ float g_bufB[N_MAX * D];
__device__ int   g_deg[N_MAX];
__device__ int   g_off[N_MAX];
__device__ int   g_cursor[N_MAX];
__device__ int   g_csr[E_MAX];
__device__ int   g_bsums[128];
// pre-split, pre-swizzled bf16 weight images: [layer][W1/W2][hi/lo][32KB]
__device__ __align__(16) unsigned char g_wimg[3][2][2][32768];

// ---------------- helpers ----------------------------------------------------
__device__ __forceinline__ uint32_t smem_u32(const void* p) {
    uint32_t a;
    asm("{ .reg .u64 t; cvta.to.shared.u64 t, %1; cvt.u32.u64 %0, t; }" : "=r"(a) : "l"(p));
    return a;
}

__device__ __forceinline__ void split2(float a, float b, uint32_t& h, uint32_t& l) {
    __nv_bfloat16 ha = __float2bfloat16(a), hb = __float2bfloat16(b);
    float ra = a - __bfloat162float(ha), rb = b - __bfloat162float(hb);
    __nv_bfloat16 la = __float2bfloat16(ra), lb = __float2bfloat16(rb);
    h = (uint32_t)(*(uint16_t*)&ha) | ((uint32_t)(*(uint16_t*)&hb) << 16);
    l = (uint32_t)(*(uint16_t*)&la) | ((uint32_t)(*(uint16_t*)&lb) << 16);
}

__device__ __forceinline__ void mma16816(float* d, uint32_t a0, uint32_t a1,
                                         uint32_t a2, uint32_t a3,
                                         uint32_t b0, uint32_t b1) {
    asm volatile(
        "mma.sync.aligned.m16n8k16.row.col.f32.bf16.bf16.f32 "
        "{%0,%1,%2,%3}, {%4,%5,%6,%7}, {%8,%9}, {%0,%1,%2,%3};"
        : "+f"(d[0]), "+f"(d[1]), "+f"(d[2]), "+f"(d[3])
        : "r"(a0), "r"(a1), "r"(a2), "r"(a3), "r"(b0), "r"(b1));
}

// ---------------- CSR build -------------------------------------------------
__global__ void k_count_deg(const int* __restrict__ dst, int* __restrict__ deg, int e) {
    int i = blockIdx.x * blockDim.x + threadIdx.x;
    if (i < e) atomicAdd(&deg[dst[i]], 1);
}

__global__ void k_scan_block(const int* __restrict__ deg, int* __restrict__ off,
                             int* __restrict__ bsums, int n) {
    __shared__ int warp_sums[32];
    int tid = threadIdx.x;
    int gid = blockIdx.x * 1024 + tid;
    int v = (gid < n) ? deg[gid] : 0;
    int x = v;
#pragma unroll
    for (int s = 1; s < 32; s <<= 1) {
        int y = __shfl_up_sync(0xffffffffu, x, s);
        if ((tid & 31) >= s) x += y;
    }
    if ((tid & 31) == 31) warp_sums[tid >> 5] = x;
    __syncthreads();
    if (tid < 32) {
        int w = warp_sums[tid];
        int xw = w;
#pragma unroll
        for (int s = 1; s < 32; s <<= 1) {
            int y = __shfl_up_sync(0xffffffffu, xw, s);
            if (tid >= s) xw += y;
        }
        warp_sums[tid] = xw - w;
        if (tid == 31) bsums[blockIdx.x] = xw;
    }
    __syncthreads();
    int excl = x - v + warp_sums[tid >> 5];
    if (gid < n) off[gid] = excl;
}

__global__ void k_add_offsets(int* __restrict__ off, int* __restrict__ cursor,
                              const int* __restrict__ bsums, int n) {
    __shared__ int sbase;
    int g = blockIdx.x >> 2;
    if (threadIdx.x < 32) {
        int s = 0;
        for (int j = threadIdx.x; j < g; j += 32) s += bsums[j];
#pragma unroll
        for (int sh = 16; sh > 0; sh >>= 1) s += __shfl_xor_sync(0xffffffffu, s, sh);
        if (threadIdx.x == 0) sbase = s;
    }
    __syncthreads();
    int i = blockIdx.x * blockDim.x + threadIdx.x;
    if (i < n) {
        int o = off[i] + sbase;
        off[i] = o;
        cursor[i] = o;
    }
}

__global__ void k_csr_fill(const int* __restrict__ src, const int* __restrict__ dst,
                           int* __restrict__ cursor, int* __restrict__ csr, int e) {
    int i = blockIdx.x * blockDim.x + threadIdx.x;
    if (i < e) {
        int pos = atomicAdd(&cursor[dst[i]], 1);
        csr[pos] = src[i];
    }
}

// ---------------- weight conversion -----------------------------------------
__global__ void k_wconv(const float* __restrict__ W1, const float* __restrict__ W2) {
    int b = blockIdx.x;
    const float* W = ((b & 1) ? W2 : W1) + (b >> 1) * D * D;
    unsigned char* hi = g_wimg[b >> 1][b & 1][0];
    unsigned char* lo = g_wimg[b >> 1][b & 1][1];
    for (int i = threadIdx.x; i < D * D; i += blockDim.x) {
        int k = i >> 7, nn = i & 127;
        float x = W[k * 128 + nn];
        __nv_bfloat16 h = __float2bfloat16(x);
        float r = x - __bfloat162float(h);
        __nv_bfloat16 l = __float2bfloat16(r);
        uint32_t off = (uint32_t)k * 256 + ((((nn >> 3) ^ (k & 7)) & 15) << 4)
                     + ((nn & 7) << 1);
        *(__nv_bfloat16*)(hi + off) = h;
        *(__nv_bfloat16*)(lo + off) = l;
    }
}

// ---------------- aggregation: warp/node, named 8-deep, NO launch-bounds cap -
__global__ void k_aggregate_z(const float* __restrict__ h,
                              const int* __restrict__ off,
                              const int* __restrict__ deg,
                              const int* __restrict__ csr,
                              const float* __restrict__ eps, int l,
                              float* __restrict__ z, int n) {
    int warp = (blockIdx.x * blockDim.x + threadIdx.x) >> 5;
    int lane = threadIdx.x & 31;
    if (warp >= n) return;
    int start = off[warp];
    int d = deg[warp];
    float inv = 1.0f / (float)((d > 0) ? d : 1);
    const float4* h4 = (const float4*)h;

    float4 acc = make_float4(0.f, 0.f, 0.f, 0.f);
    int j = 0;
    for (; j + 8 <= d; j += 8) {
        int nb0 = csr[start + j + 0];
        int nb1 = csr[start + j + 1];
        int nb2 = csr[start + j + 2];
        int nb3 = csr[start + j + 3];
        int nb4 = csr[start + j + 4];
        int nb5 = csr[start + j + 5];
        int nb6 = csr[start + j + 6];
        int nb7 = csr[start + j + 7];
        float4 v0 = __ldg(&h4[nb0 * 32 + lane]);
        float4 v1 = __ldg(&h4[nb1 * 32 + lane]);
        float4 v2 = __ldg(&h4[nb2 * 32 + lane]);
        float4 v3 = __ldg(&h4[nb3 * 32 + lane]);
        float4 v4 = __ldg(&h4[nb4 * 32 + lane]);
        float4 v5 = __ldg(&h4[nb5 * 32 + lane]);
        float4 v6 = __ldg(&h4[nb6 * 32 + lane]);
        float4 v7 = __ldg(&h4[nb7 * 32 + lane]);
        acc.x += ((v0.x + v1.x) + (v2.x + v3.x)) + ((v4.x + v5.x) + (v6.x + v7.x));
        acc.y += ((v0.y + v1.y) + (v2.y + v3.y)) + ((v4.y + v5.y) + (v6.y + v7.y));
        acc.z += ((v0.z + v1.z) + (v2.z + v3.z)) + ((v4.z + v5.z) + (v6.z + v7.z));
        acc.w += ((v0.w + v1.w) + (v2.w + v3.w)) + ((v4.w + v5.w) + (v6.w + v7.w));
    }
    if (j + 4 <= d) {
        int nb0 = csr[start + j + 0];
        int nb1 = csr[start + j + 1];
        int nb2 = csr[start + j + 2];
        int nb3 = csr[start + j + 3];
        float4 v0 = __ldg(&h4[nb0 * 32 + lane]);
        float4 v1 = __ldg(&h4[nb1 * 32 + lane]);
        float4 v2 = __ldg(&h4[nb2 * 32 + lane]);
        float4 v3 = __ldg(&h4[nb3 * 32 + lane]);
        acc.x += (v0.x + v1.x) + (v2.x + v3.x);
        acc.y += (v0.y + v1.y) + (v2.y + v3.y);
        acc.z += (v0.z + v1.z) + (v2.z + v3.z);
        acc.w += (v0.w + v1.w) + (v2.w + v3.w);
        j += 4;
    }
    for (; j < d; ++j) {
        int nb = csr[start + j];
        float4 v = __ldg(&h4[nb * 32 + lane]);
        acc.x += v.x; acc.y += v.y; acc.z += v.z; acc.w += v.w;
    }
    float e1 = 1.0f + eps[l];
    float4 hv = h4[(size_t)warp * 32 + lane];
    float4 zz;
    zz.x = e1 * hv.x + inv * acc.x;
    zz.y = e1 * hv.y + inv * acc.y;
    zz.z = e1 * hv.z + inv * acc.z;
    zz.w = e1 * hv.w + inv * acc.w;
    ((float4*)z)[(size_t)warp * 32 + lane] = zz;
}

// ---------------- persistent fused MLP (proven R5 kernel) --------------------
#define OFF_BIAS1 0
#define OFF_BIAS2 512
#define OFF_WOUT  1024
#define OFF_PROJ  2048
#define OFF_AHI   4096
#define A_STRIDE  272
#define OFF_ALO   (OFF_AHI + 128 * A_STRIDE)
#define OFF_W1HI  (OFF_ALO + 128 * A_STRIDE)
#define OFF_W1LO  (OFF_W1HI + 32768)
#define OFF_W2HI  (OFF_W1LO + 32768)
#define OFF_W2LO  (OFF_W2HI + 32768)
#define SMEM_FUSED (OFF_W2LO + 32768)   // 204800

struct MmaCtx {
    uint32_t smem_base;
    uint32_t aRowByte;
    uint32_t bRowByte;
    uint32_t bChunkBase;
    uint32_t bChunkXor;
};

__device__ __forceinline__ void mma_stage(float acc[2][8][4], const MmaCtx& cx,
                                          uint32_t aHi, uint32_t aLo,
                                          uint32_t wHi, uint32_t wLo) {
#pragma unroll
    for (int pass = 0; pass < 3; ++pass) {
        uint32_t aBase = cx.smem_base + ((pass == 2) ? aLo : aHi) + cx.aRowByte;
        uint32_t wBase = cx.smem_base + ((pass == 1) ? wLo : wHi) + cx.bRowByte;
#pragma unroll
        for (int ks = 0; ks < 8; ++ks) {
            uint32_t a0, a1, a2, a3, c0, c1, c2, c3;
            asm volatile(
                "ldmatrix.sync.aligned.m8n8.x4.shared.b16 {%0,%1,%2,%3}, [%4];"
                : "=r"(a0), "=r"(a1), "=r"(a2), "=r"(a3)
                : "r"(aBase + ks * 32));
            asm volatile(
                "ldmatrix.sync.aligned.m8n8.x4.shared.b16 {%0,%1,%2,%3}, [%4];"
                : "=r"(c0), "=r"(c1), "=r"(c2), "=r"(c3)
                : "r"(aBase + 16 * A_STRIDE + ks * 32));
#pragma unroll
            for (int j = 0; j < 4; ++j) {
                uint32_t chunk = ((cx.bChunkBase + (uint32_t)(j * 2)) ^ cx.bChunkXor) & 15u;
                uint32_t b0, b1, b2, b3;
                asm volatile(
                    "ldmatrix.sync.aligned.m8n8.x4.trans.shared.b16 {%0,%1,%2,%3}, [%4];"
                    : "=r"(b0), "=r"(b1), "=r"(b2), "=r"(b3)
                    : "r"(wBase + ks * 4096 + chunk * 16));
                mma16816(acc[0][2 * j],     a0, a1, a2, a3, b0, b1);
                mma16816(acc[0][2 * j + 1], a0, a1, a2, a3, b2, b3);
                mma16816(acc[1][2 * j],     c0, c1, c2, c3, b0, b1);
                mma16816(acc[1][2 * j + 1], c0, c1, c2, c3, b2, b3);
            }
        }
    }
}

__global__ void __launch_bounds__(256, 1)
k_mlp_persist(const float* __restrict__ Ain,
              const unsigned char* __restrict__ w1hi, const unsigned char* __restrict__ w1lo,
              const unsigned char* __restrict__ w2hi, const unsigned char* __restrict__ w2lo,
              const float* __restrict__ b1, const float* __restrict__ b2,
              float* __restrict__ Out, int n,
              int doProj, const float* __restrict__ Wout,
              const float* __restrict__ bout, float* __restrict__ nout) {
    extern __shared__ unsigned char sm[];
    uint32_t smem_base = smem_u32(sm);
    int t = threadIdx.x, w = t >> 5, lane = t & 31;
    int wm = w & 3, wn = w >> 2;

    if (t < 128) {
        ((float*)(sm + OFF_BIAS1))[t] = b1[t];
        ((float*)(sm + OFF_BIAS2))[t] = b2[t];
    }
    if (doProj) {
        ((float*)(sm + OFF_WOUT))[t] = Wout[t];
        if (t < 128) ((float*)(sm + OFF_WOUT))[128 + t] = Wout[128 + t];
    }
    {
        const uint4* s1 = (const uint4*)w1hi;
        const uint4* s2 = (const uint4*)w1lo;
        const uint4* s3 = (const uint4*)w2hi;
        const uint4* s4 = (const uint4*)w2lo;
        uint4* d1 = (uint4*)(sm + OFF_W1HI);
        uint4* d2 = (uint4*)(sm + OFF_W1LO);
        uint4* d3 = (uint4*)(sm + OFF_W2HI);
        uint4* d4 = (uint4*)(sm + OFF_W2LO);
#pragma unroll
        for (int i = 0; i < 8; ++i) {
            int j = t + i * 256;
            d1[j] = __ldg(&s1[j]);
            d2[j] = __ldg(&s2[j]);
            d3[j] = __ldg(&s3[j]);
            d4[j] = __ldg(&s4[j]);
        }
    }

    MmaCtx cx;
    cx.smem_base = smem_base;
    {
        uint32_t mRow = (uint32_t)(wm * 32) + (lane & 7) + ((lane >> 3) & 1) * 8;
        uint32_t kHalf = (lane >> 4) & 1;
        cx.aRowByte = mRow * A_STRIDE + kHalf * 16;
        uint32_t bk = (lane & 7) + ((lane >> 3) & 1) * 8;
        cx.bRowByte = bk * 256;
        cx.bChunkBase = (uint32_t)(wn * 8) + ((lane >> 4) & 1);
        cx.bChunkXor = bk & 7;
    }

    const int rowInWarp = lane >> 2;
    const int colBase = wn * 64 + (lane & 3) * 2;
    const int nTiles = (n + 127) >> 7;

    for (int tile = blockIdx.x; tile < nTiles; tile += gridDim.x) {
        int row0 = tile * 128;
        __syncthreads();

        {
            const float4* A4 = (const float4*)Ain;
#pragma unroll
            for (int i = 0; i < 16; ++i) {
                int j = t + i * 256;
                int row = j >> 5, ch = j & 31;
                int gr = row0 + row;
                float4 v = make_float4(0.f, 0.f, 0.f, 0.f);
                if (gr < n) v = __ldg(&A4[(size_t)gr * 32 + ch]);
                uint32_t h01, h23, l01, l23;
                split2(v.x, v.y, h01, l01);
                split2(v.z, v.w, h23, l23);
                *(uint2*)(sm + OFF_AHI + row * A_STRIDE + ch * 8) = make_uint2(h01, h23);
                *(uint2*)(sm + OFF_ALO + row * A_STRIDE + ch * 8) = make_uint2(l01, l23);
            }
        }
        __syncthreads();

        float acc[2][8][4];
#pragma unroll
        for (int mt = 0; mt < 2; ++mt)
#pragma unroll
            for (int f = 0; f < 8; ++f)
#pragma unroll
                for (int q = 0; q < 4; ++q) acc[mt][f][q] = 0.f;

        mma_stage(acc, cx, OFF_AHI, OFF_ALO, OFF_W1HI, OFF_W1LO);
        __syncthreads();

        const float* bias1 = (const float*)(sm + OFF_BIAS1);
#pragma unroll
        for (int mt = 0; mt < 2; ++mt) {
            int r0 = wm * 32 + mt * 16 + rowInWarp;
            int r1 = r0 + 8;
#pragma unroll
            for (int f = 0; f < 8; ++f) {
                int c = colBase + f * 8;
                float x0 = acc[mt][f][0] + bias1[c];
                float x1 = acc[mt][f][1] + bias1[c + 1];
                float y0 = acc[mt][f][2] + bias1[c];
                float y1 = acc[mt][f][3] + bias1[c + 1];
                x0 = (x0 > 0.f) ? x0 : 0.01f * x0;
                x1 = (x1 > 0.f) ? x1 : 0.01f * x1;
                y0 = (y0 > 0.f) ? y0 : 0.01f * y0;
                y1 = (y1 > 0.f) ? y1 : 0.01f * y1;
                uint32_t h, lw;
                split2(x0, x1, h, lw);
                *(uint32_t*)(sm + OFF_AHI + r0 * A_STRIDE + c * 2) = h;
                *(uint32_t*)(sm + OFF_ALO + r0 * A_STRIDE + c * 2) = lw;
                split2(y0, y1, h, lw);
                *(uint32_t*)(sm + OFF_AHI + r1 * A_STRIDE + c * 2) = h;
                *(uint32_t*)(sm + OFF_ALO + r1 * A_STRIDE + c * 2) = lw;
                acc[mt][f][0] = acc[mt][f][1] = acc[mt][f][2] = acc[mt][f][3] = 0.f;
            }
        }
        __syncthreads();

        mma_stage(acc, cx, OFF_AHI, OFF_ALO, OFF_W2HI, OFF_W2LO);

        const float* bias2 = (const float*)(sm + OFF_BIAS2);
        const float* WoutS = (const float*)(sm + OFF_WOUT);
        float* projS = (float*)(sm + OFF_PROJ);
        float s[2][2][2];
#pragma unroll
        for (int mt = 0; mt < 2; ++mt)
#pragma unroll
            for (int rr = 0; rr < 2; ++rr) { s[mt][rr][0] = 0.f; s[mt][rr][1] = 0.f; }

#pragma unroll
        for (int mt = 0; mt < 2; ++mt) {
            int r0 = wm * 32 + mt * 16 + rowInWarp;
            int r1 = r0 + 8;
            int gr0 = row0 + r0, gr1 = row0 + r1;
#pragma unroll
            for (int f = 0; f < 8; ++f) {
                int c = colBase + f * 8;
                float x0 = acc[mt][f][0] + bias2[c];
                float x1 = acc[mt][f][1] + bias2[c + 1];
                float y0 = acc[mt][f][2] + bias2[c];
                float y1 = acc[mt][f][3] + bias2[c + 1];
                x0 = (x0 > 0.f) ? x0 : 0.01f * x0;
                x1 = (x1 > 0.f) ? x1 : 0.01f * x1;
                y0 = (y0 > 0.f) ? y0 : 0.01f * y0;
                y1 = (y1 > 0.f) ? y1 : 0.01f * y1;
                if (gr0 < n) *(float2*)(Out + (size_t)gr0 * 128 + c) = make_float2(x0, x1);
                if (gr1 < n) *(float2*)(Out + (size_t)gr1 * 128 + c) = make_float2(y0, y1);
                if (doProj) {
                    float w0 = WoutS[c * 2],     o0 = WoutS[c * 2 + 1];
                    float w1 = WoutS[c * 2 + 2], o1 = WoutS[c * 2 + 3];
                    s[mt][0][0] += x0 * w0 + x1 * w1;
                    s[mt][0][1] += x0 * o0 + x1 * o1;
                    s[mt][1][0] += y0 * w0 + y1 * w1;
                    s[mt][1][1] += y0 * o0 + y1 * o1;
                }
            }
        }
        if (doProj) {
#pragma unroll
            for (int sh = 1; sh <= 2; sh <<= 1) {
#pragma unroll
                for (int mt = 0; mt < 2; ++mt)
#pragma unroll
                    for (int rr = 0; rr < 2; ++rr) {
                        s[mt][rr][0] += __shfl_xor_sync(0xffffffffu, s[mt][rr][0], sh);
                        s[mt][rr][1] += __shfl_xor_sync(0xffffffffu, s[mt][rr][1], sh);
                    }
            }
            if ((lane & 3) == 0) {
#pragma unroll
                for (int mt = 0; mt < 2; ++mt) {
                    int r0 = wm * 32 + mt * 16 + rowInWarp;
#pragma unroll
                    for (int rr = 0; rr < 2; ++rr) {
                        int r = r0 + rr * 8;
                        projS[(r * 2 + 0) * 2 + wn] = s[mt][rr][0];
                        projS[(r * 2 + 1) * 2 + wn] = s[mt][rr][1];
                    }
                }
            }
            __syncthreads();
            if (t < 128) {
                int gr = row0 + t;
                if (gr < n) {
                    float bo0 = __ldg(&bout[0]), bo1 = __ldg(&bout[1]);
                    nout[(size_t)gr * 2 + 0] = projS[(t * 2 + 0) * 2] + projS[(t * 2 + 0) * 2 + 1] + bo0;
                    nout[(size_t)gr * 2 + 1] = projS[(t * 2 + 1) * 2] + projS[(t * 2 + 1) * 2 + 1] + bo1;
                }
            }
        }
    }
}

// ---------------- launch ------------------------------------------------------
extern "C" void kernel_launch(void* const* d_in, const int* in_sizes, int n_in,
                              void* d_out, int out_size) {
    const float* x    = (const float*)d_in[0];
    const int*   src  = (const int*)d_in[1];
    const int*   dst  = (const int*)d_in[2];
    const float* W1   = (const float*)d_in[3];
    const float* b1   = (const float*)d_in[4];
    const float* W2   = (const float*)d_in[5];
    const float* b2   = (const float*)d_in[6];
    const float* eps  = (const float*)d_in[7];
    const float* Wout = (const float*)d_in[8];
    const float* bout = (const float*)d_in[9];

    const int n = in_sizes[0] / D;
    const int e = in_sizes[1];

    float* nout = (float*)d_out;                 // [n, 2]
    float* emb  = (float*)d_out + (size_t)n * 2; // [n, 128]

    float *bufA, *bufB;
    int *deg, *off, *cursor, *csr, *bsums;
    unsigned char* wimg;
    cudaGetSymbolAddress((void**)&bufA,   g_bufA);
    cudaGetSymbolAddress((void**)&bufB,   g_bufB);
    cudaGetSymbolAddress((void**)&deg,    g_deg);
    cudaGetSymbolAddress((void**)&off,    g_off);
    cudaGetSymbolAddress((void**)&cursor, g_cursor);
    cudaGetSymbolAddress((void**)&csr,    g_csr);
    cudaGetSymbolAddress((void**)&bsums,  g_bsums);
    cudaGetSymbolAddress((void**)&wimg,   g_wimg);

    cudaFuncSetAttribute(k_mlp_persist,
                         cudaFuncAttributeMaxDynamicSharedMemorySize, SMEM_FUSED);

    // ---- CSR build ----
    cudaMemsetAsync(deg, 0, n * sizeof(int));
    k_count_deg<<<(e + 255) / 256, 256>>>(dst, deg, e);
    int nb = (n + 1023) / 1024;
    k_scan_block<<<nb, 1024>>>(deg, off, bsums, n);
    k_add_offsets<<<(n + 255) / 256, 256>>>(off, cursor, bsums, n);
    k_csr_fill<<<(e + 255) / 256, 256>>>(src, dst, cursor, csr, e);

    // ---- weight conversion ----
    k_wconv<<<6, 256>>>(W1, W2);

    const int agg_blocks = (n * 32 + 255) / 256;
    const int mlp_grid = 152;
    auto wp = [&](int l, int which, int part) -> unsigned char* {
        return wimg + (((size_t)l * 2 + which) * 2 + part) * 32768;
    };

    // layer 0: agg(x)->bufA ; mlp(bufA)->bufB
    k_aggregate_z<<<agg_blocks, 256>>>(x, off, deg, csr, eps, 0, bufA, n);
    k_mlp_persist<<<mlp_grid, 256, SMEM_FUSED>>>(bufA,
        wp(0, 0, 0), wp(0, 0, 1), wp(0, 1, 0), wp(0, 1, 1),
        b1 + 0 * D, b2 + 0 * D, bufB, n, 0, Wout, bout, nout);

    // layer 1
    k_aggregate_z<<<agg_blocks, 256>>>(bufB, off, deg, csr, eps, 1, bufA, n);
    k_mlp_persist<<<mlp_grid, 256, SMEM_FUSED>>>(bufA,
        wp(1, 0, 0), wp(1, 0, 1), wp(1, 1, 0), wp(1, 1, 1),
        b1 + 1 * D, b2 + 1 * D, bufB, n, 0, Wout, bout, nout);

    // layer 2 -> emb, fused output projection
    k_aggregate_z<<<agg_blocks, 256>>>(bufB, off, deg, csr, eps, 2, bufA, n);
    k_mlp_persist<<<mlp_grid, 256, SMEM_FUSED>>>(bufA,
        wp(2, 0, 0), wp(2, 0, 1), wp(2, 1, 0), wp(2, 1, 1),
        b1 + 2 * D, b2 + 2 * D, emb, n, 1, Wout, bout, nout);
}

// round 16
// speedup vs baseline: 1.0321x; 1.0321x over previous
#include <cuda_runtime.h>
#include <cuda_bf16.h>
#include <cstdint>

#define N_MAX 100000
#define E_MAX 1600000
#define D 128

// ---------------- scratch (device globals; no allocation allowed) ----------
__device__ float g_bufA[N_MAX * D];
__device__ float g_bufB[N_MAX * D];
__device__ int   g_deg[N_MAX];
__device__ int   g_off[N_MAX];
__device__ int   g_cursor[N_MAX];
__device__ int   g_csr[E_MAX];
__device__ int   g_bsums[128];
// pre-split, pre-swizzled bf16 weight images: [layer][W1/W2][hi/lo][32KB]
__device__ __align__(16) unsigned char g_wimg[3][2][2][32768];

// ---------------- helpers ----------------------------------------------------
__device__ __forceinline__ uint32_t smem_u32(const void* p) {
    uint32_t a;
    asm("{ .reg .u64 t; cvta.to.shared.u64 t, %1; cvt.u32.u64 %0, t; }" : "=r"(a) : "l"(p));
    return a;
}

__device__ __forceinline__ void split2(float a, float b, uint32_t& h, uint32_t& l) {
    __nv_bfloat16 ha = __float2bfloat16(a), hb = __float2bfloat16(b);
    float ra = a - __bfloat162float(ha), rb = b - __bfloat162float(hb);
    __nv_bfloat16 la = __float2bfloat16(ra), lb = __float2bfloat16(rb);
    h = (uint32_t)(*(uint16_t*)&ha) | ((uint32_t)(*(uint16_t*)&hb) << 16);
    l = (uint32_t)(*(uint16_t*)&la) | ((uint32_t)(*(uint16_t*)&lb) << 16);
}

__device__ __forceinline__ void mma16816(float* d, uint32_t a0, uint32_t a1,
                                         uint32_t a2, uint32_t a3,
                                         uint32_t b0, uint32_t b1) {
    asm volatile(
        "mma.sync.aligned.m16n8k16.row.col.f32.bf16.bf16.f32 "
        "{%0,%1,%2,%3}, {%4,%5,%6,%7}, {%8,%9}, {%0,%1,%2,%3};"
        : "+f"(d[0]), "+f"(d[1]), "+f"(d[2]), "+f"(d[3])
        : "r"(a0), "r"(a1), "r"(a2), "r"(a3), "r"(b0), "r"(b1));
}

// ---------------- CSR build -------------------------------------------------
__global__ void k_count_deg(const int* __restrict__ dst, int* __restrict__ deg, int e) {
    int i = blockIdx.x * blockDim.x + threadIdx.x;
    if (i < e) atomicAdd(&deg[dst[i]], 1);
}

__global__ void k_scan_block(const int* __restrict__ deg, int* __restrict__ off,
                             int* __restrict__ bsums, int n) {
    __shared__ int warp_sums[32];
    int tid = threadIdx.x;
    int gid = blockIdx.x * 1024 + tid;
    int v = (gid < n) ? deg[gid] : 0;
    int x = v;
#pragma unroll
    for (int s = 1; s < 32; s <<= 1) {
        int y = __shfl_up_sync(0xffffffffu, x, s);
        if ((tid & 31) >= s) x += y;
    }
    if ((tid & 31) == 31) warp_sums[tid >> 5] = x;
    __syncthreads();
    if (tid < 32) {
        int w = warp_sums[tid];
        int xw = w;
#pragma unroll
        for (int s = 1; s < 32; s <<= 1) {
            int y = __shfl_up_sync(0xffffffffu, xw, s);
            if (tid >= s) xw += y;
        }
        warp_sums[tid] = xw - w;
        if (tid == 31) bsums[blockIdx.x] = xw;
    }
    __syncthreads();
    int excl = x - v + warp_sums[tid >> 5];
    if (gid < n) off[gid] = excl;
}

__global__ void k_add_offsets(int* __restrict__ off, int* __restrict__ cursor,
                              const int* __restrict__ bsums, int n) {
    __shared__ int sbase;
    int g = blockIdx.x >> 2;
    if (threadIdx.x < 32) {
        int s = 0;
        for (int j = threadIdx.x; j < g; j += 32) s += bsums[j];
#pragma unroll
        for (int sh = 16; sh > 0; sh >>= 1) s += __shfl_xor_sync(0xffffffffu, s, sh);
        if (threadIdx.x == 0) sbase = s;
    }
    __syncthreads();
    int i = blockIdx.x * blockDim.x + threadIdx.x;
    if (i < n) {
        int o = off[i] + sbase;
        off[i] = o;
        cursor[i] = o;
    }
}

__global__ void k_csr_fill(const int* __restrict__ src, const int* __restrict__ dst,
                           int* __restrict__ cursor, int* __restrict__ csr, int e) {
    int i = blockIdx.x * blockDim.x + threadIdx.x;
    if (i < e) {
        int pos = atomicAdd(&cursor[dst[i]], 1);
        csr[pos] = src[i];
    }
}

// ---------------- weight conversion -----------------------------------------
__global__ void k_wconv(const float* __restrict__ W1, const float* __restrict__ W2) {
    int b = blockIdx.x;
    const float* W = ((b & 1) ? W2 : W1) + (b >> 1) * D * D;
    unsigned char* hi = g_wimg[b >> 1][b & 1][0];
    unsigned char* lo = g_wimg[b >> 1][b & 1][1];
    for (int i = threadIdx.x; i < D * D; i += blockDim.x) {
        int k = i >> 7, nn = i & 127;
        float x = W[k * 128 + nn];
        __nv_bfloat16 h = __float2bfloat16(x);
        float r = x - __bfloat162float(h);
        __nv_bfloat16 l = __float2bfloat16(r);
        uint32_t off = (uint32_t)k * 256 + ((((nn >> 3) ^ (k & 7)) & 15) << 4)
                     + ((nn & 7) << 1);
        *(__nv_bfloat16*)(hi + off) = h;
        *(__nv_bfloat16*)(lo + off) = l;
    }
}

// ---------------- aggregation (proven R5 kernel, warp per node, unroll-4) ---
__global__ void k_aggregate_z(const float* __restrict__ h,
                              const int* __restrict__ off,
                              const int* __restrict__ deg,
                              const int* __restrict__ csr,
                              const float* __restrict__ eps, int l,
                              float* __restrict__ z, int n) {
    int warp = (blockIdx.x * blockDim.x + threadIdx.x) >> 5;
    int lane = threadIdx.x & 31;
    if (warp >= n) return;
    int start = off[warp];
    int d = deg[warp];
    float inv = 1.0f / (float)((d > 0) ? d : 1);
    const float4* h4 = (const float4*)h;

    float4 acc = make_float4(0.f, 0.f, 0.f, 0.f);
    int j = 0;
    for (; j + 4 <= d; j += 4) {
        int nb0 = csr[start + j + 0];
        int nb1 = csr[start + j + 1];
        int nb2 = csr[start + j + 2];
        int nb3 = csr[start + j + 3];
        float4 v0 = __ldg(&h4[nb0 * 32 + lane]);
        float4 v1 = __ldg(&h4[nb1 * 32 + lane]);
        float4 v2 = __ldg(&h4[nb2 * 32 + lane]);
        float4 v3 = __ldg(&h4[nb3 * 32 + lane]);
        acc.x += v0.x + v1.x + v2.x + v3.x;
        acc.y += v0.y + v1.y + v2.y + v3.y;
        acc.z += v0.z + v1.z + v2.z + v3.z;
        acc.w += v0.w + v1.w + v2.w + v3.w;
    }
    for (; j < d; ++j) {
        int nb = csr[start + j];
        float4 v = __ldg(&h4[nb * 32 + lane]);
        acc.x += v.x; acc.y += v.y; acc.z += v.z; acc.w += v.w;
    }
    float e1 = 1.0f + eps[l];
    float4 hv = h4[warp * 32 + lane];
    float4 zz;
    zz.x = e1 * hv.x + inv * acc.x;
    zz.y = e1 * hv.y + inv * acc.y;
    zz.z = e1 * hv.z + inv * acc.z;
    zz.w = e1 * hv.w + inv * acc.w;
    ((float4*)z)[warp * 32 + lane] = zz;
}

// ---------------- persistent fused MLP (proven R5 kernel) --------------------
#define OFF_BIAS1 0
#define OFF_BIAS2 512
#define OFF_WOUT  1024
#define OFF_PROJ  2048
#define OFF_AHI   4096
#define A_STRIDE  272
#define OFF_ALO   (OFF_AHI + 128 * A_STRIDE)
#define OFF_W1HI  (OFF_ALO + 128 * A_STRIDE)
#define OFF_W1LO  (OFF_W1HI + 32768)
#define OFF_W2HI  (OFF_W1LO + 32768)
#define OFF_W2LO  (OFF_W2HI + 32768)
#define SMEM_FUSED (OFF_W2LO + 32768)   // 204800

struct MmaCtx {
    uint32_t smem_base;
    uint32_t aRowByte;
    uint32_t bRowByte;
    uint32_t bChunkBase;
    uint32_t bChunkXor;
};

__device__ __forceinline__ void mma_stage(float acc[2][8][4], const MmaCtx& cx,
                                          uint32_t aHi, uint32_t aLo,
                                          uint32_t wHi, uint32_t wLo) {
#pragma unroll
    for (int pass = 0; pass < 3; ++pass) {
        uint32_t aBase = cx.smem_base + ((pass == 2) ? aLo : aHi) + cx.aRowByte;
        uint32_t wBase = cx.smem_base + ((pass == 1) ? wLo : wHi) + cx.bRowByte;
#pragma unroll
        for (int ks = 0; ks < 8; ++ks) {
            uint32_t a0, a1, a2, a3, c0, c1, c2, c3;
            asm volatile(
                "ldmatrix.sync.aligned.m8n8.x4.shared.b16 {%0,%1,%2,%3}, [%4];"
                : "=r"(a0), "=r"(a1), "=r"(a2), "=r"(a3)
                : "r"(aBase + ks * 32));
            asm volatile(
                "ldmatrix.sync.aligned.m8n8.x4.shared.b16 {%0,%1,%2,%3}, [%4];"
                : "=r"(c0), "=r"(c1), "=r"(c2), "=r"(c3)
                : "r"(aBase + 16 * A_STRIDE + ks * 32));
#pragma unroll
            for (int j = 0; j < 4; ++j) {
                uint32_t chunk = ((cx.bChunkBase + (uint32_t)(j * 2)) ^ cx.bChunkXor) & 15u;
                uint32_t b0, b1, b2, b3;
                asm volatile(
                    "ldmatrix.sync.aligned.m8n8.x4.trans.shared.b16 {%0,%1,%2,%3}, [%4];"
                    : "=r"(b0), "=r"(b1), "=r"(b2), "=r"(b3)
                    : "r"(wBase + ks * 4096 + chunk * 16));
                mma16816(acc[0][2 * j],     a0, a1, a2, a3, b0, b1);
                mma16816(acc[0][2 * j + 1], a0, a1, a2, a3, b2, b3);
                mma16816(acc[1][2 * j],     c0, c1, c2, c3, b0, b1);
                mma16816(acc[1][2 * j + 1], c0, c1, c2, c3, b2, b3);
            }
        }
    }
}

__global__ void __launch_bounds__(256, 1)
k_mlp_persist(const float* __restrict__ Ain,
              const unsigned char* __restrict__ w1hi, const unsigned char* __restrict__ w1lo,
              const unsigned char* __restrict__ w2hi, const unsigned char* __restrict__ w2lo,
              const float* __restrict__ b1, const float* __restrict__ b2,
              float* __restrict__ Out, int n,
              int doProj, const float* __restrict__ Wout,
              const float* __restrict__ bout, float* __restrict__ nout) {
    extern __shared__ unsigned char sm[];
    uint32_t smem_base = smem_u32(sm);
    int t = threadIdx.x, w = t >> 5, lane = t & 31;
    int wm = w & 3, wn = w >> 2;

    if (t < 128) {
        ((float*)(sm + OFF_BIAS1))[t] = b1[t];
        ((float*)(sm + OFF_BIAS2))[t] = b2[t];
    }
    if (doProj) {
        ((float*)(sm + OFF_WOUT))[t] = Wout[t];
        if (t < 128) ((float*)(sm + OFF_WOUT))[128 + t] = Wout[128 + t];
    }
    {
        const uint4* s1 = (const uint4*)w1hi;
        const uint4* s2 = (const uint4*)w1lo;
        const uint4* s3 = (const uint4*)w2hi;
        const uint4* s4 = (const uint4*)w2lo;
        uint4* d1 = (uint4*)(sm + OFF_W1HI);
        uint4* d2 = (uint4*)(sm + OFF_W1LO);
        uint4* d3 = (uint4*)(sm + OFF_W2HI);
        uint4* d4 = (uint4*)(sm + OFF_W2LO);
#pragma unroll
        for (int i = 0; i < 8; ++i) {
            int j = t + i * 256;
            d1[j] = __ldg(&s1[j]);
            d2[j] = __ldg(&s2[j]);
            d3[j] = __ldg(&s3[j]);
            d4[j] = __ldg(&s4[j]);
        }
    }

    MmaCtx cx;
    cx.smem_base = smem_base;
    {
        uint32_t mRow = (uint32_t)(wm * 32) + (lane & 7) + ((lane >> 3) & 1) * 8;
        uint32_t kHalf = (lane >> 4) & 1;
        cx.aRowByte = mRow * A_STRIDE + kHalf * 16;
        uint32_t bk = (lane & 7) + ((lane >> 3) & 1) * 8;
        cx.bRowByte = bk * 256;
        cx.bChunkBase = (uint32_t)(wn * 8) + ((lane >> 4) & 1);
        cx.bChunkXor = bk & 7;
    }

    const int rowInWarp = lane >> 2;
    const int colBase = wn * 64 + (lane & 3) * 2;
    const int nTiles = (n + 127) >> 7;

    for (int tile = blockIdx.x; tile < nTiles; tile += gridDim.x) {
        int row0 = tile * 128;
        __syncthreads();

        {
            const float4* A4 = (const float4*)Ain;
#pragma unroll
            for (int i = 0; i < 16; ++i) {
                int j = t + i * 256;
                int row = j >> 5, ch = j & 31;
                int gr = row0 + row;
                float4 v = make_float4(0.f, 0.f, 0.f, 0.f);
                if (gr < n) v = __ldg(&A4[(size_t)gr * 32 + ch]);
                uint32_t h01, h23, l01, l23;
                split2(v.x, v.y, h01, l01);
                split2(v.z, v.w, h23, l23);
                *(uint2*)(sm + OFF_AHI + row * A_STRIDE + ch * 8) = make_uint2(h01, h23);
                *(uint2*)(sm + OFF_ALO + row * A_STRIDE + ch * 8) = make_uint2(l01, l23);
            }
        }
        __syncthreads();

        float acc[2][8][4];
#pragma unroll
        for (int mt = 0; mt < 2; ++mt)
#pragma unroll
            for (int f = 0; f < 8; ++f)
#pragma unroll
                for (int q = 0; q < 4; ++q) acc[mt][f][q] = 0.f;

        mma_stage(acc, cx, OFF_AHI, OFF_ALO, OFF_W1HI, OFF_W1LO);
        __syncthreads();

        const float* bias1 = (const float*)(sm + OFF_BIAS1);
#pragma unroll
        for (int mt = 0; mt < 2; ++mt) {
            int r0 = wm * 32 + mt * 16 + rowInWarp;
            int r1 = r0 + 8;
#pragma unroll
            for (int f = 0; f < 8; ++f) {
                int c = colBase + f * 8;
                float x0 = acc[mt][f][0] + bias1[c];
                float x1 = acc[mt][f][1] + bias1[c + 1];
                float y0 = acc[mt][f][2] + bias1[c];
                float y1 = acc[mt][f][3] + bias1[c + 1];
                x0 = (x0 > 0.f) ? x0 : 0.01f * x0;
                x1 = (x1 > 0.f) ? x1 : 0.01f * x1;
                y0 = (y0 > 0.f) ? y0 : 0.01f * y0;
                y1 = (y1 > 0.f) ? y1 : 0.01f * y1;
                uint32_t h, lw;
                split2(x0, x1, h, lw);
                *(uint32_t*)(sm + OFF_AHI + r0 * A_STRIDE + c * 2) = h;
                *(uint32_t*)(sm + OFF_ALO + r0 * A_STRIDE + c * 2) = lw;
                split2(y0, y1, h, lw);
                *(uint32_t*)(sm + OFF_AHI + r1 * A_STRIDE + c * 2) = h;
                *(uint32_t*)(sm + OFF_ALO + r1 * A_STRIDE + c * 2) = lw;
                acc[mt][f][0] = acc[mt][f][1] = acc[mt][f][2] = acc[mt][f][3] = 0.f;
            }
        }
        __syncthreads();

        mma_stage(acc, cx, OFF_AHI, OFF_ALO, OFF_W2HI, OFF_W2LO);

        const float* bias2 = (const float*)(sm + OFF_BIAS2);
        const float* WoutS = (const float*)(sm + OFF_WOUT);
        float* projS = (float*)(sm + OFF_PROJ);
        float s[2][2][2];
#pragma unroll
        for (int mt = 0; mt < 2; ++mt)
#pragma unroll
            for (int rr = 0; rr < 2; ++rr) { s[mt][rr][0] = 0.f; s[mt][rr][1] = 0.f; }

#pragma unroll
        for (int mt = 0; mt < 2; ++mt) {
            int r0 = wm * 32 + mt * 16 + rowInWarp;
            int r1 = r0 + 8;
            int gr0 = row0 + r0, gr1 = row0 + r1;
#pragma unroll
            for (int f = 0; f < 8; ++f) {
                int c = colBase + f * 8;
                float x0 = acc[mt][f][0] + bias2[c];
                float x1 = acc[mt][f][1] + bias2[c + 1];
                float y0 = acc[mt][f][2] + bias2[c];
                float y1 = acc[mt][f][3] + bias2[c + 1];
                x0 = (x0 > 0.f) ? x0 : 0.01f * x0;
                x1 = (x1 > 0.f) ? x1 : 0.01f * x1;
                y0 = (y0 > 0.f) ? y0 : 0.01f * y0;
                y1 = (y1 > 0.f) ? y1 : 0.01f * y1;
                if (gr0 < n) *(float2*)(Out + (size_t)gr0 * 128 + c) = make_float2(x0, x1);
                if (gr1 < n) *(float2*)(Out + (size_t)gr1 * 128 + c) = make_float2(y0, y1);
                if (doProj) {
                    float w0 = WoutS[c * 2],     o0 = WoutS[c * 2 + 1];
                    float w1 = WoutS[c * 2 + 2], o1 = WoutS[c * 2 + 3];
                    s[mt][0][0] += x0 * w0 + x1 * w1;
                    s[mt][0][1] += x0 * o0 + x1 * o1;
                    s[mt][1][0] += y0 * w0 + y1 * w1;
                    s[mt][1][1] += y0 * o0 + y1 * o1;
                }
            }
        }
        if (doProj) {
#pragma unroll
            for (int sh = 1; sh <= 2; sh <<= 1) {
#pragma unroll
                for (int mt = 0; mt < 2; ++mt)
#pragma unroll
                    for (int rr = 0; rr < 2; ++rr) {
                        s[mt][rr][0] += __shfl_xor_sync(0xffffffffu, s[mt][rr][0], sh);
                        s[mt][rr][1] += __shfl_xor_sync(0xffffffffu, s[mt][rr][1], sh);
                    }
            }
            if ((lane & 3) == 0) {
#pragma unroll
                for (int mt = 0; mt < 2; ++mt) {
                    int r0 = wm * 32 + mt * 16 + rowInWarp;
#pragma unroll
                    for (int rr = 0; rr < 2; ++rr) {
                        int r = r0 + rr * 8;
                        projS[(r * 2 + 0) * 2 + wn] = s[mt][rr][0];
                        projS[(r * 2 + 1) * 2 + wn] = s[mt][rr][1];
                    }
                }
            }
            __syncthreads();
            if (t < 128) {
                int gr = row0 + t;
                if (gr < n) {
                    float bo0 = __ldg(&bout[0]), bo1 = __ldg(&bout[1]);
                    nout[(size_t)gr * 2 + 0] = projS[(t * 2 + 0) * 2] + projS[(t * 2 + 0) * 2 + 1] + bo0;
                    nout[(size_t)gr * 2 + 1] = projS[(t * 2 + 1) * 2] + projS[(t * 2 + 1) * 2 + 1] + bo1;
                }
            }
        }
    }
}

// ---------------- launch ------------------------------------------------------
extern "C" void kernel_launch(void* const* d_in, const int* in_sizes, int n_in,
                              void* d_out, int out_size) {
    const float* x    = (const float*)d_in[0];
    const int*   src  = (const int*)d_in[1];
    const int*   dst  = (const int*)d_in[2];
    const float* W1   = (const float*)d_in[3];
    const float* b1   = (const float*)d_in[4];
    const float* W2   = (const float*)d_in[5];
    const float* b2   = (const float*)d_in[6];
    const float* eps  = (const float*)d_in[7];
    const float* Wout = (const float*)d_in[8];
    const float* bout = (const float*)d_in[9];

    const int n = in_sizes[0] / D;
    const int e = in_sizes[1];

    float* nout = (float*)d_out;                 // [n, 2]
    float* emb  = (float*)d_out + (size_t)n * 2; // [n, 128]

    float *bufA, *bufB;
    int *deg, *off, *cursor, *csr, *bsums;
    unsigned char* wimg;
    cudaGetSymbolAddress((void**)&bufA,   g_bufA);
    cudaGetSymbolAddress((void**)&bufB,   g_bufB);
    cudaGetSymbolAddress((void**)&deg,    g_deg);
    cudaGetSymbolAddress((void**)&off,    g_off);
    cudaGetSymbolAddress((void**)&cursor, g_cursor);
    cudaGetSymbolAddress((void**)&csr,    g_csr);
    cudaGetSymbolAddress((void**)&bsums,  g_bsums);
    cudaGetSymbolAddress((void**)&wimg,   g_wimg);

    cudaFuncSetAttribute(k_mlp_persist,
                         cudaFuncAttributeMaxDynamicSharedMemorySize, SMEM_FUSED);

    // ---- CSR build ----
    cudaMemsetAsync(deg, 0, n * sizeof(int));
    k_count_deg<<<(e + 255) / 256, 256>>>(dst, deg, e);
    int nb = (n + 1023) / 1024;
    k_scan_block<<<nb, 1024>>>(deg, off, bsums, n);
    k_add_offsets<<<(n + 255) / 256, 256>>>(off, cursor, bsums, n);
    k_csr_fill<<<(e + 255) / 256, 256>>>(src, dst, cursor, csr, e);

    // ---- weight conversion ----
    k_wconv<<<6, 256>>>(W1, W2);

    const int agg_blocks = (n * 32 + 255) / 256;
    const int mlp_grid = 152;
    auto wp = [&](int l, int which, int part) -> unsigned char* {
        return wimg + (((size_t)l * 2 + which) * 2 + part) * 32768;
    };

    // layer 0: agg(x)->bufA ; mlp(bufA)->bufB
    k_aggregate_z<<<agg_blocks, 256>>>(x, off, deg, csr, eps, 0, bufA, n);
    k_mlp_persist<<<mlp_grid, 256, SMEM_FUSED>>>(bufA,
        wp(0, 0, 0), wp(0, 0, 1), wp(0, 1, 0), wp(0, 1, 1),
        b1 + 0 * D, b2 + 0 * D, bufB, n, 0, Wout, bout, nout);

    // layer 1
    k_aggregate_z<<<agg_blocks, 256>>>(bufB, off, deg, csr, eps, 1, bufA, n);
    k_mlp_persist<<<mlp_grid, 256, SMEM_FUSED>>>(bufA,
        wp(1, 0, 0), wp(1, 0, 1), wp(1, 1, 0), wp(1, 1, 1),
        b1 + 1 * D, b2 + 1 * D, bufB, n, 0, Wout, bout, nout);

    // layer 2 -> emb, fused output projection
    k_aggregate_z<<<agg_blocks, 256>>>(bufB, off, deg, csr, eps, 2, bufA, n);
    k_mlp_persist<<<mlp_grid, 256, SMEM_FUSED>>>(bufA,
        wp(2, 0, 0), wp(2, 0, 1), wp(2, 1, 0), wp(2, 1, 1),
        b1 + 2 * D, b2 + 2 * D, emb, n, 1, Wout, bout, nout);
}

// round 17
// speedup vs baseline: 1.0641x; 1.0311x over previous
#include <cuda_runtime.h>
#include <cuda_bf16.h>
#include <cstdint>

#define N_MAX 100000
#define E_MAX 1600000
#define D 128

// ---------------- scratch (device globals; no allocation allowed) ----------
__device__ float g_bufA[N_MAX * D];
__device__ float g_bufB[N_MAX * D];
__device__ int   g_deg[N_MAX];
__device__ int   g_off[N_MAX];
__device__ int   g_cursor[N_MAX];
__device__ int   g_csr[E_MAX];
__device__ int   g_bsums[128];
// pre-split, pre-swizzled bf16 weight images: [layer][W1/W2][hi/lo][32KB]
__device__ __align__(16) unsigned char g_wimg[3][2][2][32768];

// ---------------- helpers ----------------------------------------------------
__device__ __forceinline__ uint32_t smem_u32(const void* p) {
    uint32_t a;
    asm("{ .reg .u64 t; cvta.to.shared.u64 t, %1; cvt.u32.u64 %0, t; }" : "=r"(a) : "l"(p));
    return a;
}

__device__ __forceinline__ void split2(float a, float b, uint32_t& h, uint32_t& l) {
    __nv_bfloat16 ha = __float2bfloat16(a), hb = __float2bfloat16(b);
    float ra = a - __bfloat162float(ha), rb = b - __bfloat162float(hb);
    __nv_bfloat16 la = __float2bfloat16(ra), lb = __float2bfloat16(rb);
    h = (uint32_t)(*(uint16_t*)&ha) | ((uint32_t)(*(uint16_t*)&hb) << 16);
    l = (uint32_t)(*(uint16_t*)&la) | ((uint32_t)(*(uint16_t*)&lb) << 16);
}

__device__ __forceinline__ void mma16816(float* d, uint32_t a0, uint32_t a1,
                                         uint32_t a2, uint32_t a3,
                                         uint32_t b0, uint32_t b1) {
    asm volatile(
        "mma.sync.aligned.m16n8k16.row.col.f32.bf16.bf16.f32 "
        "{%0,%1,%2,%3}, {%4,%5,%6,%7}, {%8,%9}, {%0,%1,%2,%3};"
        : "+f"(d[0]), "+f"(d[1]), "+f"(d[2]), "+f"(d[3])
        : "r"(a0), "r"(a1), "r"(a2), "r"(a3), "r"(b0), "r"(b1));
}

// ---------------- CSR build -------------------------------------------------
__global__ void k_count_deg(const int* __restrict__ dst, int* __restrict__ deg, int e) {
    int i = blockIdx.x * blockDim.x + threadIdx.x;
    if (i < e) atomicAdd(&deg[dst[i]], 1);
}

__global__ void k_scan_block(const int* __restrict__ deg, int* __restrict__ off,
                             int* __restrict__ bsums, int n) {
    __shared__ int warp_sums[32];
    int tid = threadIdx.x;
    int gid = blockIdx.x * 1024 + tid;
    int v = (gid < n) ? deg[gid] : 0;
    int x = v;
#pragma unroll
    for (int s = 1; s < 32; s <<= 1) {
        int y = __shfl_up_sync(0xffffffffu, x, s);
        if ((tid & 31) >= s) x += y;
    }
    if ((tid & 31) == 31) warp_sums[tid >> 5] = x;
    __syncthreads();
    if (tid < 32) {
        int w = warp_sums[tid];
        int xw = w;
#pragma unroll
        for (int s = 1; s < 32; s <<= 1) {
            int y = __shfl_up_sync(0xffffffffu, xw, s);
            if (tid >= s) xw += y;
        }
        warp_sums[tid] = xw - w;
        if (tid == 31) bsums[blockIdx.x] = xw;
    }
    __syncthreads();
    int excl = x - v + warp_sums[tid >> 5];
    if (gid < n) off[gid] = excl;
}

__global__ void k_add_offsets(int* __restrict__ off, int* __restrict__ cursor,
                              const int* __restrict__ bsums, int n) {
    __shared__ int sbase;
    int g = blockIdx.x >> 2;
    if (threadIdx.x < 32) {
        int s = 0;
        for (int j = threadIdx.x; j < g; j += 32) s += bsums[j];
#pragma unroll
        for (int sh = 16; sh > 0; sh >>= 1) s += __shfl_xor_sync(0xffffffffu, s, sh);
        if (threadIdx.x == 0) sbase = s;
    }
    __syncthreads();
    int i = blockIdx.x * blockDim.x + threadIdx.x;
    if (i < n) {
        int o = off[i] + sbase;
        off[i] = o;
        cursor[i] = o;
    }
}

__global__ void k_csr_fill(const int* __restrict__ src, const int* __restrict__ dst,
                           int* __restrict__ cursor, int* __restrict__ csr, int e) {
    int i = blockIdx.x * blockDim.x + threadIdx.x;
    if (i < e) {
        int pos = atomicAdd(&cursor[dst[i]], 1);
        csr[pos] = src[i];
    }
}

// ---------------- weight conversion -----------------------------------------
__global__ void k_wconv(const float* __restrict__ W1, const float* __restrict__ W2) {
    int b = blockIdx.x;
    const float* W = ((b & 1) ? W2 : W1) + (b >> 1) * D * D;
    unsigned char* hi = g_wimg[b >> 1][b & 1][0];
    unsigned char* lo = g_wimg[b >> 1][b & 1][1];
    for (int i = threadIdx.x; i < D * D; i += blockDim.x) {
        int k = i >> 7, nn = i & 127;
        float x = W[k * 128 + nn];
        __nv_bfloat16 h = __float2bfloat16(x);
        float r = x - __bfloat162float(h);
        __nv_bfloat16 l = __float2bfloat16(r);
        uint32_t off = (uint32_t)k * 256 + ((((nn >> 3) ^ (k & 7)) & 15) << 4)
                     + ((nn & 7) << 1);
        *(__nv_bfloat16*)(hi + off) = h;
        *(__nv_bfloat16*)(lo + off) = l;
    }
}

// ---------------- aggregation (proven R5 kernel, warp per node, unroll-4) ---
__global__ void k_aggregate_z(const float* __restrict__ h,
                              const int* __restrict__ off,
                              const int* __restrict__ deg,
                              const int* __restrict__ csr,
                              const float* __restrict__ eps, int l,
                              float* __restrict__ z, int n) {
    int warp = (blockIdx.x * blockDim.x + threadIdx.x) >> 5;
    int lane = threadIdx.x & 31;
    if (warp >= n) return;
    int start = off[warp];
    int d = deg[warp];
    float inv = 1.0f / (float)((d > 0) ? d : 1);
    const float4* h4 = (const float4*)h;

    float4 acc = make_float4(0.f, 0.f, 0.f, 0.f);
    int j = 0;
    for (; j + 4 <= d; j += 4) {
        int nb0 = csr[start + j + 0];
        int nb1 = csr[start + j + 1];
        int nb2 = csr[start + j + 2];
        int nb3 = csr[start + j + 3];
        float4 v0 = __ldg(&h4[nb0 * 32 + lane]);
        float4 v1 = __ldg(&h4[nb1 * 32 + lane]);
        float4 v2 = __ldg(&h4[nb2 * 32 + lane]);
        float4 v3 = __ldg(&h4[nb3 * 32 + lane]);
        acc.x += v0.x + v1.x + v2.x + v3.x;
        acc.y += v0.y + v1.y + v2.y + v3.y;
        acc.z += v0.z + v1.z + v2.z + v3.z;
        acc.w += v0.w + v1.w + v2.w + v3.w;
    }
    for (; j < d; ++j) {
        int nb = csr[start + j];
        float4 v = __ldg(&h4[nb * 32 + lane]);
        acc.x += v.x; acc.y += v.y; acc.z += v.z; acc.w += v.w;
    }
    float e1 = 1.0f + eps[l];
    float4 hv = h4[warp * 32 + lane];
    float4 zz;
    zz.x = e1 * hv.x + inv * acc.x;
    zz.y = e1 * hv.y + inv * acc.y;
    zz.z = e1 * hv.z + inv * acc.z;
    zz.w = e1 * hv.w + inv * acc.w;
    ((float4*)z)[warp * 32 + lane] = zz;
}

// ---------------- persistent fused MLP ---------------------------------------
// k-step-outer 3-pass MMA: each fragment loaded ONCE per k-step (96 vs 144 LDSM)
#define OFF_BIAS1 0
#define OFF_BIAS2 512
#define OFF_WOUT  1024
#define OFF_PROJ  2048
#define OFF_AHI   4096
#define A_STRIDE  272
#define OFF_ALO   (OFF_AHI + 128 * A_STRIDE)
#define OFF_W1HI  (OFF_ALO + 128 * A_STRIDE)
#define OFF_W1LO  (OFF_W1HI + 32768)
#define OFF_W2HI  (OFF_W1LO + 32768)
#define OFF_W2LO  (OFF_W2HI + 32768)
#define SMEM_FUSED (OFF_W2LO + 32768)   // 204800

struct MmaCtx {
    uint32_t smem_base;
    uint32_t aRowByte;
    uint32_t bRowByte;
    uint32_t bChunkBase;
    uint32_t bChunkXor;
};

__device__ __forceinline__ void mma_stage(float acc[2][8][4], const MmaCtx& cx,
                                          uint32_t aHi, uint32_t aLo,
                                          uint32_t wHi, uint32_t wLo) {
    uint32_t aHiB = cx.smem_base + aHi + cx.aRowByte;
    uint32_t aLoB = cx.smem_base + aLo + cx.aRowByte;
    uint32_t wHiB = cx.smem_base + wHi + cx.bRowByte;
    uint32_t wLoB = cx.smem_base + wLo + cx.bRowByte;
#pragma unroll
    for (int ks = 0; ks < 8; ++ks) {
        // A fragments: hi/lo planes x 2 m-tiles, loaded once per k-step
        uint32_t h00, h01, h02, h03, h10, h11, h12, h13;
        uint32_t l00, l01, l02, l03, l10, l11, l12, l13;
        asm volatile(
            "ldmatrix.sync.aligned.m8n8.x4.shared.b16 {%0,%1,%2,%3}, [%4];"
            : "=r"(h00), "=r"(h01), "=r"(h02), "=r"(h03)
            : "r"(aHiB + ks * 32));
        asm volatile(
            "ldmatrix.sync.aligned.m8n8.x4.shared.b16 {%0,%1,%2,%3}, [%4];"
            : "=r"(h10), "=r"(h11), "=r"(h12), "=r"(h13)
            : "r"(aHiB + 16 * A_STRIDE + ks * 32));
        asm volatile(
            "ldmatrix.sync.aligned.m8n8.x4.shared.b16 {%0,%1,%2,%3}, [%4];"
            : "=r"(l00), "=r"(l01), "=r"(l02), "=r"(l03)
            : "r"(aLoB + ks * 32));
        asm volatile(
            "ldmatrix.sync.aligned.m8n8.x4.shared.b16 {%0,%1,%2,%3}, [%4];"
            : "=r"(l10), "=r"(l11), "=r"(l12), "=r"(l13)
            : "r"(aLoB + 16 * A_STRIDE + ks * 32));
#pragma unroll
        for (int j = 0; j < 4; ++j) {
            uint32_t chunk = ((cx.bChunkBase + (uint32_t)(j * 2)) ^ cx.bChunkXor) & 15u;
            uint32_t bh0, bh1, bh2, bh3, bl0, bl1, bl2, bl3;
            asm volatile(
                "ldmatrix.sync.aligned.m8n8.x4.trans.shared.b16 {%0,%1,%2,%3}, [%4];"
                : "=r"(bh0), "=r"(bh1), "=r"(bh2), "=r"(bh3)
                : "r"(wHiB + ks * 4096 + chunk * 16));
            asm volatile(
                "ldmatrix.sync.aligned.m8n8.x4.trans.shared.b16 {%0,%1,%2,%3}, [%4];"
                : "=r"(bl0), "=r"(bl1), "=r"(bl2), "=r"(bl3)
                : "r"(wLoB + ks * 4096 + chunk * 16));
            // pass hh: A_hi x W_hi
            mma16816(acc[0][2 * j],     h00, h01, h02, h03, bh0, bh1);
            mma16816(acc[0][2 * j + 1], h00, h01, h02, h03, bh2, bh3);
            mma16816(acc[1][2 * j],     h10, h11, h12, h13, bh0, bh1);
            mma16816(acc[1][2 * j + 1], h10, h11, h12, h13, bh2, bh3);
            // pass hl: A_hi x W_lo
            mma16816(acc[0][2 * j],     h00, h01, h02, h03, bl0, bl1);
            mma16816(acc[0][2 * j + 1], h00, h01, h02, h03, bl2, bl3);
            mma16816(acc[1][2 * j],     h10, h11, h12, h13, bl0, bl1);
            mma16816(acc[1][2 * j + 1], h10, h11, h12, h13, bl2, bl3);
            // pass lh: A_lo x W_hi
            mma16816(acc[0][2 * j],     l00, l01, l02, l03, bh0, bh1);
            mma16816(acc[0][2 * j + 1], l00, l01, l02, l03, bh2, bh3);
            mma16816(acc[1][2 * j],     l10, l11, l12, l13, bh0, bh1);
            mma16816(acc[1][2 * j + 1], l10, l11, l12, l13, bh2, bh3);
        }
    }
}

__global__ void __launch_bounds__(256, 1)
k_mlp_persist(const float* __restrict__ Ain,
              const unsigned char* __restrict__ w1hi, const unsigned char* __restrict__ w1lo,
              const unsigned char* __restrict__ w2hi, const unsigned char* __restrict__ w2lo,
              const float* __restrict__ b1, const float* __restrict__ b2,
              float* __restrict__ Out, int n,
              int doProj, const float* __restrict__ Wout,
              const float* __restrict__ bout, float* __restrict__ nout) {
    extern __shared__ unsigned char sm[];
    uint32_t smem_base = smem_u32(sm);
    int t = threadIdx.x, w = t >> 5, lane = t & 31;
    int wm = w & 3, wn = w >> 2;

    if (t < 128) {
        ((float*)(sm + OFF_BIAS1))[t] = b1[t];
        ((float*)(sm + OFF_BIAS2))[t] = b2[t];
    }
    if (doProj) {
        ((float*)(sm + OFF_WOUT))[t] = Wout[t];
        if (t < 128) ((float*)(sm + OFF_WOUT))[128 + t] = Wout[128 + t];
    }
    {
        const uint4* s1 = (const uint4*)w1hi;
        const uint4* s2 = (const uint4*)w1lo;
        const uint4* s3 = (const uint4*)w2hi;
        const uint4* s4 = (const uint4*)w2lo;
        uint4* d1 = (uint4*)(sm + OFF_W1HI);
        uint4* d2 = (uint4*)(sm + OFF_W1LO);
        uint4* d3 = (uint4*)(sm + OFF_W2HI);
        uint4* d4 = (uint4*)(sm + OFF_W2LO);
#pragma unroll
        for (int i = 0; i < 8; ++i) {
            int j = t + i * 256;
            d1[j] = __ldg(&s1[j]);
            d2[j] = __ldg(&s2[j]);
            d3[j] = __ldg(&s3[j]);
            d4[j] = __ldg(&s4[j]);
        }
    }

    MmaCtx cx;
    cx.smem_base = smem_base;
    {
        uint32_t mRow = (uint32_t)(wm * 32) + (lane & 7) + ((lane >> 3) & 1) * 8;
        uint32_t kHalf = (lane >> 4) & 1;
        cx.aRowByte = mRow * A_STRIDE + kHalf * 16;
        uint32_t bk = (lane & 7) + ((lane >> 3) & 1) * 8;
        cx.bRowByte = bk * 256;
        cx.bChunkBase = (uint32_t)(wn * 8) + ((lane >> 4) & 1);
        cx.bChunkXor = bk & 7;
    }

    const int rowInWarp = lane >> 2;
    const int colBase = wn * 64 + (lane & 3) * 2;
    const int nTiles = (n + 127) >> 7;

    for (int tile = blockIdx.x; tile < nTiles; tile += gridDim.x) {
        int row0 = tile * 128;
        __syncthreads();

        {
            const float4* A4 = (const float4*)Ain;
#pragma unroll
            for (int i = 0; i < 16; ++i) {
                int j = t + i * 256;
                int row = j >> 5, ch = j & 31;
                int gr = row0 + row;
                float4 v = make_float4(0.f, 0.f, 0.f, 0.f);
                if (gr < n) v = __ldg(&A4[(size_t)gr * 32 + ch]);
                uint32_t h01, h23, l01, l23;
                split2(v.x, v.y, h01, l01);
                split2(v.z, v.w, h23, l23);
                *(uint2*)(sm + OFF_AHI + row * A_STRIDE + ch * 8) = make_uint2(h01, h23);
                *(uint2*)(sm + OFF_ALO + row * A_STRIDE + ch * 8) = make_uint2(l01, l23);
            }
        }
        __syncthreads();

        float acc[2][8][4];
#pragma unroll
        for (int mt = 0; mt < 2; ++mt)
#pragma unroll
            for (int f = 0; f < 8; ++f)
#pragma unroll
                for (int q = 0; q < 4; ++q) acc[mt][f][q] = 0.f;

        mma_stage(acc, cx, OFF_AHI, OFF_ALO, OFF_W1HI, OFF_W1LO);
        __syncthreads();

        const float* bias1 = (const float*)(sm + OFF_BIAS1);
#pragma unroll
        for (int mt = 0; mt < 2; ++mt) {
            int r0 = wm * 32 + mt * 16 + rowInWarp;
            int r1 = r0 + 8;
#pragma unroll
            for (int f = 0; f < 8; ++f) {
                int c = colBase + f * 8;
                float x0 = acc[mt][f][0] + bias1[c];
                float x1 = acc[mt][f][1] + bias1[c + 1];
                float y0 = acc[mt][f][2] + bias1[c];
                float y1 = acc[mt][f][3] + bias1[c + 1];
                x0 = (x0 > 0.f) ? x0 : 0.01f * x0;
                x1 = (x1 > 0.f) ? x1 : 0.01f * x1;
                y0 = (y0 > 0.f) ? y0 : 0.01f * y0;
                y1 = (y1 > 0.f) ? y1 : 0.01f * y1;
                uint32_t h, lw;
                split2(x0, x1, h, lw);
                *(uint32_t*)(sm + OFF_AHI + r0 * A_STRIDE + c * 2) = h;
                *(uint32_t*)(sm + OFF_ALO + r0 * A_STRIDE + c * 2) = lw;
                split2(y0, y1, h, lw);
                *(uint32_t*)(sm + OFF_AHI + r1 * A_STRIDE + c * 2) = h;
                *(uint32_t*)(sm + OFF_ALO + r1 * A_STRIDE + c * 2) = lw;
                acc[mt][f][0] = acc[mt][f][1] = acc[mt][f][2] = acc[mt][f][3] = 0.f;
            }
        }
        __syncthreads();

        mma_stage(acc, cx, OFF_AHI, OFF_ALO, OFF_W2HI, OFF_W2LO);

        const float* bias2 = (const float*)(sm + OFF_BIAS2);
        const float* WoutS = (const float*)(sm + OFF_WOUT);
        float* projS = (float*)(sm + OFF_PROJ);
        float s[2][2][2];
#pragma unroll
        for (int mt = 0; mt < 2; ++mt)
#pragma unroll
            for (int rr = 0; rr < 2; ++rr) { s[mt][rr][0] = 0.f; s[mt][rr][1] = 0.f; }

#pragma unroll
        for (int mt = 0; mt < 2; ++mt) {
            int r0 = wm * 32 + mt * 16 + rowInWarp;
            int r1 = r0 + 8;
            int gr0 = row0 + r0, gr1 = row0 + r1;
#pragma unroll
            for (int f = 0; f < 8; ++f) {
                int c = colBase + f * 8;
                float x0 = acc[mt][f][0] + bias2[c];
                float x1 = acc[mt][f][1] + bias2[c + 1];
                float y0 = acc[mt][f][2] + bias2[c];
                float y1 = acc[mt][f][3] + bias2[c + 1];
                x0 = (x0 > 0.f) ? x0 : 0.01f * x0;
                x1 = (x1 > 0.f) ? x1 : 0.01f * x1;
                y0 = (y0 > 0.f) ? y0 : 0.01f * y0;
                y1 = (y1 > 0.f) ? y1 : 0.01f * y1;
                if (gr0 < n) *(float2*)(Out + (size_t)gr0 * 128 + c) = make_float2(x0, x1);
                if (gr1 < n) *(float2*)(Out + (size_t)gr1 * 128 + c) = make_float2(y0, y1);
                if (doProj) {
                    float w0 = WoutS[c * 2],     o0 = WoutS[c * 2 + 1];
                    float w1 = WoutS[c * 2 + 2], o1 = WoutS[c * 2 + 3];
                    s[mt][0][0] += x0 * w0 + x1 * w1;
                    s[mt][0][1] += x0 * o0 + x1 * o1;
                    s[mt][1][0] += y0 * w0 + y1 * w1;
                    s[mt][1][1] += y0 * o0 + y1 * o1;
                }
            }
        }
        if (doProj) {
#pragma unroll
            for (int sh = 1; sh <= 2; sh <<= 1) {
#pragma unroll
                for (int mt = 0; mt < 2; ++mt)
#pragma unroll
                    for (int rr = 0; rr < 2; ++rr) {
                        s[mt][rr][0] += __shfl_xor_sync(0xffffffffu, s[mt][rr][0], sh);
                        s[mt][rr][1] += __shfl_xor_sync(0xffffffffu, s[mt][rr][1], sh);
                    }
            }
            if ((lane & 3) == 0) {
#pragma unroll
                for (int mt = 0; mt < 2; ++mt) {
                    int r0 = wm * 32 + mt * 16 + rowInWarp;
#pragma unroll
                    for (int rr = 0; rr < 2; ++rr) {
                        int r = r0 + rr * 8;
                        projS[(r * 2 + 0) * 2 + wn] = s[mt][rr][0];
                        projS[(r * 2 + 1) * 2 + wn] = s[mt][rr][1];
                    }
                }
            }
            __syncthreads();
            if (t < 128) {
                int gr = row0 + t;
                if (gr < n) {
                    float bo0 = __ldg(&bout[0]), bo1 = __ldg(&bout[1]);
                    nout[(size_t)gr * 2 + 0] = projS[(t * 2 + 0) * 2] + projS[(t * 2 + 0) * 2 + 1] + bo0;
                    nout[(size_t)gr * 2 + 1] = projS[(t * 2 + 1) * 2] + projS[(t * 2 + 1) * 2 + 1] + bo1;
                }
            }
        }
    }
}

// ---------------- launch ------------------------------------------------------
extern "C" void kernel_launch(void* const* d_in, const int* in_sizes, int n_in,
                              void* d_out, int out_size) {
    const float* x    = (const float*)d_in[0];
    const int*   src  = (const int*)d_in[1];
    const int*   dst  = (const int*)d_in[2];
    const float* W1   = (const float*)d_in[3];
    const float* b1   = (const float*)d_in[4];
    const float* W2   = (const float*)d_in[5];
    const float* b2   = (const float*)d_in[6];
    const float* eps  = (const float*)d_in[7];
    const float* Wout = (const float*)d_in[8];
    const float* bout = (const float*)d_in[9];

    const int n = in_sizes[0] / D;
    const int e = in_sizes[1];

    float* nout = (float*)d_out;                 // [n, 2]
    float* emb  = (float*)d_out + (size_t)n * 2; // [n, 128]

    float *bufA, *bufB;
    int *deg, *off, *cursor, *csr, *bsums;
    unsigned char* wimg;
    cudaGetSymbolAddress((void**)&bufA,   g_bufA);
    cudaGetSymbolAddress((void**)&bufB,   g_bufB);
    cudaGetSymbolAddress((void**)&deg,    g_deg);
    cudaGetSymbolAddress((void**)&off,    g_off);
    cudaGetSymbolAddress((void**)&cursor, g_cursor);
    cudaGetSymbolAddress((void**)&csr,    g_csr);
    cudaGetSymbolAddress((void**)&bsums,  g_bsums);
    cudaGetSymbolAddress((void**)&wimg,   g_wimg);

    cudaFuncSetAttribute(k_mlp_persist,
                         cudaFuncAttributeMaxDynamicSharedMemorySize, SMEM_FUSED);

    // ---- CSR build ----
    cudaMemsetAsync(deg, 0, n * sizeof(int));
    k_count_deg<<<(e + 255) / 256, 256>>>(dst, deg, e);
    int nb = (n + 1023) / 1024;
    k_scan_block<<<nb, 1024>>>(deg, off, bsums, n);
    k_add_offsets<<<(n + 255) / 256, 256>>>(off, cursor, bsums, n);
    k_csr_fill<<<(e + 255) / 256, 256>>>(src, dst, cursor, csr, e);

    // ---- weight conversion ----
    k_wconv<<<6, 256>>>(W1, W2);

    const int agg_blocks = (n * 32 + 255) / 256;
    const int mlp_grid = 152;
    auto wp = [&](int l, int which, int part) -> unsigned char* {
        return wimg + (((size_t)l * 2 + which) * 2 + part) * 32768;
    };

    // layer 0: agg(x)->bufA ; mlp(bufA)->bufB
    k_aggregate_z<<<agg_blocks, 256>>>(x, off, deg, csr, eps, 0, bufA, n);
    k_mlp_persist<<<mlp_grid, 256, SMEM_FUSED>>>(bufA,
        wp(0, 0, 0), wp(0, 0, 1), wp(0, 1, 0), wp(0, 1, 1),
        b1 + 0 * D, b2 + 0 * D, bufB, n, 0, Wout, bout, nout);

    // layer 1
    k_aggregate_z<<<agg_blocks, 256>>>(bufB, off, deg, csr, eps, 1, bufA, n);
    k_mlp_persist<<<mlp_grid, 256, SMEM_FUSED>>>(bufA,
        wp(1, 0, 0), wp(1, 0, 1), wp(1, 1, 0), wp(1, 1, 1),
        b1 + 1 * D, b2 + 1 * D, bufB, n, 0, Wout, bout, nout);

    // layer 2 -> emb, fused output projection
    k_aggregate_z<<<agg_blocks, 256>>>(bufB, off, deg, csr, eps, 2, bufA, n);
    k_mlp_persist<<<mlp_grid, 256, SMEM_FUSED>>>(bufA,
        wp(2, 0, 0), wp(2, 0, 1), wp(2, 1, 0), wp(2, 1, 1),
        b1 + 2 * D, b2 + 2 * D, emb, n, 1, Wout, bout, nout);
}